// round 1
// baseline (speedup 1.0000x reference)
#include <cuda_runtime.h>

// Problem constants (fixed by the reference: B=8, T=1024, D=1024, 16 heads)
#define GB 8
#define GT 1024
#define GD 1024
#define NHEAD 16
#define HD 64
#define GM (GB * GT)   // 8192 rows

// Scratch: Q, K, V projections and attention output, each [8192, 1024] fp32.
__device__ float g_Q[GM * GD];
__device__ float g_K[GM * GD];
__device__ float g_V[GM * GD];
__device__ float g_AO[GM * GD];

// ---------------------------------------------------------------------------
// Fast exp (e^x for x <= 0, tolerant of very large negative / "-inf" stand-ins).
// FMA/ALU only — avoids MUFU.EX2, which would be the bottleneck pipe in the
// attention kernel (exp:FMA op ratio 1:128 vs pipe capacity ratio 1:256).
// Max rel error ~2.4e-6 on [-0.5,0.5] poly; plenty for 1e-3 tolerance.
// ---------------------------------------------------------------------------
__device__ __forceinline__ float fexp(float x) {
    float y = fmaxf(x * 1.4426950408889634f, -126.0f);   // log2(e), clamp
    float r = y + 12582912.0f;                            // round-to-nearest trick
    int   n = __float_as_int(r) - 0x4B400000;             // integer part of y
    float k = y - (r - 12582912.0f);                      // frac in [-0.5, 0.5]
    float p = 1.3333558146428443e-3f;
    p = fmaf(p, k, 9.618129107628477e-3f);
    p = fmaf(p, k, 5.550410866482158e-2f);
    p = fmaf(p, k, 2.402265069591007e-1f);
    p = fmaf(p, k, 6.931471805599453e-1f);
    p = fmaf(p, k, 1.0f);
    return p * __int_as_float((n + 127) << 23);           // * 2^n
}

// ---------------------------------------------------------------------------
// SGEMM (NT): C[m,n] = sum_k A[m,k] * B[n,k].  M = gridDim.y*128, N=K=1024.
// 128x128 block tile, BK=16, 256 threads, 8x8 per-thread microtile,
// double-buffered smem (one __syncthreads per k-tile).
// ---------------------------------------------------------------------------
__device__ __forceinline__ void gemm_body_nt(
    const float* __restrict__ A, const float* __restrict__ B,
    float* __restrict__ C)
{
    __shared__ float As[2][16][128];
    __shared__ float Bs[2][16][128];

    const int tid = threadIdx.x;
    const int tx = tid & 15;          // 0..15 -> n microtile
    const int ty = tid >> 4;          // 0..15 -> m microtile
    const int bm = blockIdx.y << 7;
    const int bn = blockIdx.x << 7;

    const int lrow = tid >> 2;        // 0..63 (load row within tile half)
    const int lc4  = (tid & 3) << 2;  // 0,4,8,12 (k-offset of float4)

    const float* Ap = A + (bm + lrow) * GD + lc4;
    const float* Bp = B + (bn + lrow) * GD + lc4;

    float4 ra0, ra1, rb0, rb1;
    float acc[8][8];
#pragma unroll
    for (int i = 0; i < 8; ++i)
#pragma unroll
        for (int j = 0; j < 8; ++j) acc[i][j] = 0.f;

#define LDG_T(kt) { \
        const float* ap_ = Ap + (kt) * 16; \
        const float* bp_ = Bp + (kt) * 16; \
        ra0 = *(const float4*)ap_;               \
        ra1 = *(const float4*)(ap_ + 64 * GD);   \
        rb0 = *(const float4*)bp_;               \
        rb1 = *(const float4*)(bp_ + 64 * GD);   }

#define STS_T(bf) { \
        As[bf][lc4+0][lrow] = ra0.x; As[bf][lc4+1][lrow] = ra0.y; \
        As[bf][lc4+2][lrow] = ra0.z; As[bf][lc4+3][lrow] = ra0.w; \
        As[bf][lc4+0][lrow+64] = ra1.x; As[bf][lc4+1][lrow+64] = ra1.y; \
        As[bf][lc4+2][lrow+64] = ra1.z; As[bf][lc4+3][lrow+64] = ra1.w; \
        Bs[bf][lc4+0][lrow] = rb0.x; Bs[bf][lc4+1][lrow] = rb0.y; \
        Bs[bf][lc4+2][lrow] = rb0.z; Bs[bf][lc4+3][lrow] = rb0.w; \
        Bs[bf][lc4+0][lrow+64] = rb1.x; Bs[bf][lc4+1][lrow+64] = rb1.y; \
        Bs[bf][lc4+2][lrow+64] = rb1.z; Bs[bf][lc4+3][lrow+64] = rb1.w; }

    LDG_T(0);
    STS_T(0);
    __syncthreads();

#pragma unroll 1
    for (int t = 0; t < 64; ++t) {
        const int cur = t & 1;
        if (t < 63) LDG_T(t + 1);
#pragma unroll
        for (int k = 0; k < 16; ++k) {
            float4 a0 = *(const float4*)&As[cur][k][ty << 3];
            float4 a1 = *(const float4*)&As[cur][k][(ty << 3) + 4];
            float4 b0 = *(const float4*)&Bs[cur][k][tx << 3];
            float4 b1 = *(const float4*)&Bs[cur][k][(tx << 3) + 4];
            float ar[8] = {a0.x, a0.y, a0.z, a0.w, a1.x, a1.y, a1.z, a1.w};
            float br[8] = {b0.x, b0.y, b0.z, b0.w, b1.x, b1.y, b1.z, b1.w};
#pragma unroll
            for (int i = 0; i < 8; ++i)
#pragma unroll
                for (int j = 0; j < 8; ++j)
                    acc[i][j] = fmaf(ar[i], br[j], acc[i][j]);
        }
        if (t < 63) STS_T(cur ^ 1);
        __syncthreads();
    }
#undef LDG_T
#undef STS_T

    float* Cp = C + (bm + (ty << 3)) * GD + bn + (tx << 3);
#pragma unroll
    for (int i = 0; i < 8; ++i) {
        *(float4*)(Cp + i * GD) =
            make_float4(acc[i][0], acc[i][1], acc[i][2], acc[i][3]);
        *(float4*)(Cp + i * GD + 4) =
            make_float4(acc[i][4], acc[i][5], acc[i][6], acc[i][7]);
    }
}

// z = 0 -> K, 1 -> Q, 2 -> V (matches input order x, Wk, Wq, Wv, Wo)
__global__ __launch_bounds__(256, 2)
void qkv_kernel(const float* __restrict__ x,
                const float* __restrict__ Wk,
                const float* __restrict__ Wq,
                const float* __restrict__ Wv)
{
    const float* B = (blockIdx.z == 0) ? Wk : (blockIdx.z == 1) ? Wq : Wv;
    float*       C = (blockIdx.z == 0) ? g_K : (blockIdx.z == 1) ? g_Q : g_V;
    gemm_body_nt(x, B, C);
}

__global__ __launch_bounds__(256, 2)
void oproj_kernel(const float* __restrict__ Wo, float* __restrict__ out)
{
    gemm_body_nt(g_AO, Wo, out);
}

// ---------------------------------------------------------------------------
// Flash-style causal attention, fp32.
// Block: 256 threads (16x16), one 64-query tile of one (batch, head).
// Q,K in smem TRANSPOSED [h][r] with XOR swizzle on r-granule so that:
//   - compute-phase float4 loads are conflict-free (lanes span all banks or broadcast)
//   - smem stays at exactly 48 KB static (3 x 64 x 64 fp32)
// K buffer is reused as the P (probability) tile for the P@V GEMM.
// ---------------------------------------------------------------------------
#define SWZ(rr, cc) (((cc) * 64) + ((((rr) >> 2) ^ ((cc) & 15)) << 2) + ((rr) & 3))

__global__ __launch_bounds__(256)
void flash_kernel()
{
    __shared__ float Qt[64 * 64];   // logical [h][r], swizzled
    __shared__ float Kt[64 * 64];   // logical [h][c]; reused as Pt [c][r]
    __shared__ float Vs[64 * 64];   // logical [c][hc], natural layout

    const int tid = threadIdx.x;
    const int tx = tid & 15;        // key-col / headdim-col microtile
    const int ty = tid >> 4;        // query-row microtile
    const int qt = blockIdx.x;      // query tile 0..15
    const int bh = blockIdx.y;      // b*16 + h
    const int b = bh >> 4, h = bh & 15;

    const int base = b * GT * GD + h * HD;
    const float* qg = g_Q + base + qt * 64 * GD;

    // Load Q tile transposed + swizzled
#pragma unroll
    for (int it = 0; it < 4; ++it) {
        int i = tid + it * 256;
        int r = i >> 4;
        int c4 = (i & 15) << 2;
        float4 v = *(const float4*)(qg + r * GD + c4);
        Qt[SWZ(r, c4 + 0)] = v.x;
        Qt[SWZ(r, c4 + 1)] = v.y;
        Qt[SWZ(r, c4 + 2)] = v.z;
        Qt[SWZ(r, c4 + 3)] = v.w;
    }

    float m[4], l[4], o[4][4];
#pragma unroll
    for (int i = 0; i < 4; ++i) {
        m[i] = -1e30f;
        l[i] = 0.f;
#pragma unroll
        for (int j = 0; j < 4; ++j) o[i][j] = 0.f;
    }

    const int r0 = ty << 2;
    const int c0 = tx << 2;

    for (int jt = 0; jt <= qt; ++jt) {
        const float* kg = g_K + base + jt * 64 * GD;
        const float* vg = g_V + base + jt * 64 * GD;

        __syncthreads();   // prev iteration's Pt/Vs reads done (also covers Qt init)

        // Load K (transposed+swizzled) and V (natural)
#pragma unroll
        for (int it = 0; it < 4; ++it) {
            int i = tid + it * 256;
            int r = i >> 4;
            int c4 = (i & 15) << 2;
            float4 kv = *(const float4*)(kg + r * GD + c4);
            Kt[SWZ(r, c4 + 0)] = kv.x;
            Kt[SWZ(r, c4 + 1)] = kv.y;
            Kt[SWZ(r, c4 + 2)] = kv.z;
            Kt[SWZ(r, c4 + 3)] = kv.w;
            float4 vv = *(const float4*)(vg + r * GD + c4);
            *(float4*)&Vs[r * 64 + c4] = vv;
        }
        __syncthreads();

        // S = Q K^T  (4x4 per thread)
        float s[4][4];
#pragma unroll
        for (int i = 0; i < 4; ++i)
#pragma unroll
            for (int j = 0; j < 4; ++j) s[i][j] = 0.f;

#pragma unroll 16
        for (int hh = 0; hh < 64; ++hh) {
            const int sw = hh & 15;
            float4 qa = *(const float4*)&Qt[hh * 64 + ((ty ^ sw) << 2)];
            float4 kb = *(const float4*)&Kt[hh * 64 + ((tx ^ sw) << 2)];
            float ar[4] = {qa.x, qa.y, qa.z, qa.w};
            float br[4] = {kb.x, kb.y, kb.z, kb.w};
#pragma unroll
            for (int i = 0; i < 4; ++i)
#pragma unroll
                for (int j = 0; j < 4; ++j)
                    s[i][j] = fmaf(ar[i], br[j], s[i][j]);
        }

        // scale (1/sqrt(64)) + causal mask (only the diagonal tile is partial)
        const bool diag = (jt == qt);
#pragma unroll
        for (int i = 0; i < 4; ++i)
#pragma unroll
            for (int j = 0; j < 4; ++j) {
                float v = s[i][j] * 0.125f;
                if (diag && (c0 + j) > (r0 + i)) v = -1e30f;
                s[i][j] = v;
            }

        // online softmax update (row reductions across the 16 tx lanes)
#pragma unroll
        for (int i = 0; i < 4; ++i) {
            float rm = fmaxf(fmaxf(s[i][0], s[i][1]), fmaxf(s[i][2], s[i][3]));
            rm = fmaxf(rm, __shfl_xor_sync(0xffffffffu, rm, 1));
            rm = fmaxf(rm, __shfl_xor_sync(0xffffffffu, rm, 2));
            rm = fmaxf(rm, __shfl_xor_sync(0xffffffffu, rm, 4));
            rm = fmaxf(rm, __shfl_xor_sync(0xffffffffu, rm, 8));
            float mn = fmaxf(m[i], rm);
            float alpha = fexp(m[i] - mn);
            float rs = 0.f;
#pragma unroll
            for (int j = 0; j < 4; ++j) {
                float p = fexp(s[i][j] - mn);
                s[i][j] = p;
                rs += p;
            }
            rs += __shfl_xor_sync(0xffffffffu, rs, 1);
            rs += __shfl_xor_sync(0xffffffffu, rs, 2);
            rs += __shfl_xor_sync(0xffffffffu, rs, 4);
            rs += __shfl_xor_sync(0xffffffffu, rs, 8);
            l[i] = l[i] * alpha + rs;
            m[i] = mn;
#pragma unroll
            for (int j = 0; j < 4; ++j) o[i][j] *= alpha;
        }

        __syncthreads();   // everyone done reading Kt as K before overwrite as P

        // Write P into Kt as Pt logical [c][r] (same swizzle family)
#pragma unroll
        for (int i = 0; i < 4; ++i)
#pragma unroll
            for (int j = 0; j < 4; ++j) {
                int c = c0 + j;
                Kt[c * 64 + ((ty ^ (c & 15)) << 2) + i] = s[i][j];
            }
        __syncthreads();

        // O += P @ V
#pragma unroll 8
        for (int c = 0; c < 64; ++c) {
            float4 pa = *(const float4*)&Kt[c * 64 + ((ty ^ (c & 15)) << 2)];
            float4 vb = *(const float4*)&Vs[c * 64 + (tx << 2)];
            float ar[4] = {pa.x, pa.y, pa.z, pa.w};
            float br[4] = {vb.x, vb.y, vb.z, vb.w};
#pragma unroll
            for (int i = 0; i < 4; ++i)
#pragma unroll
                for (int j = 0; j < 4; ++j)
                    o[i][j] = fmaf(ar[i], br[j], o[i][j]);
        }
    }

    // epilogue: normalize and store to attention-output scratch
    float* og = g_AO + base + qt * 64 * GD;
#pragma unroll
    for (int i = 0; i < 4; ++i) {
        float inv = 1.0f / l[i];
        float4 w = make_float4(o[i][0] * inv, o[i][1] * inv,
                               o[i][2] * inv, o[i][3] * inv);
        *(float4*)(og + (r0 + i) * GD + (tx << 2)) = w;
    }
}

// ---------------------------------------------------------------------------
// Launch: QKV projections -> flash attention -> output projection.
// Input order (metadata): x, Wk, Wq, Wv, Wo.  All launches graph-capturable,
// scratch is static __device__ memory (no allocations).
// ---------------------------------------------------------------------------
extern "C" void kernel_launch(void* const* d_in, const int* in_sizes, int n_in,
                              void* d_out, int out_size)
{
    const float* x  = (const float*)d_in[0];
    const float* Wk = (const float*)d_in[1];
    const float* Wq = (const float*)d_in[2];
    const float* Wv = (const float*)d_in[3];
    const float* Wo = (const float*)d_in[4];
    float* out = (float*)d_out;

    (void)in_sizes; (void)n_in; (void)out_size;

    qkv_kernel<<<dim3(GD / 128, GM / 128, 3), 256>>>(x, Wk, Wq, Wv);
    flash_kernel<<<dim3(GT / 64, GB * NHEAD), 256>>>();
    oproj_kernel<<<dim3(GD / 128, GM / 128), 256>>>(Wo, out);
}

// round 3
// speedup vs baseline: 1.7078x; 1.7078x over previous
#include <cuda_runtime.h>
#include <cuda_bf16.h>
#include <cstdint>

// Problem constants (fixed: B=8, T=1024, D=1024, 16 heads)
#define GB 8
#define GT 1024
#define GD 1024
#define NHEAD 16
#define HD 64
#define GM (GB * GT)   // 8192 rows

// ---------------------------------------------------------------------------
// Device scratch (no allocations allowed)
// ---------------------------------------------------------------------------
__device__ float g_Q[GM * GD];
__device__ float g_K[GM * GD];
__device__ float g_V[GM * GD];
__device__ float g_AO[GM * GD];

__device__ __nv_bfloat16 g_xh[GM * GD];
__device__ __nv_bfloat16 g_xl[GM * GD];
__device__ __nv_bfloat16 g_aoh[GM * GD];
__device__ __nv_bfloat16 g_aol[GM * GD];
__device__ __nv_bfloat16 g_Wkh[GD * GD], g_Wkl[GD * GD];
__device__ __nv_bfloat16 g_Wqh[GD * GD], g_Wql[GD * GD];
__device__ __nv_bfloat16 g_Wvh[GD * GD], g_Wvl[GD * GD];
__device__ __nv_bfloat16 g_Woh[GD * GD], g_Wol[GD * GD];

// ---------------------------------------------------------------------------
// Helpers
// ---------------------------------------------------------------------------
__device__ __forceinline__ uint32_t smem_u32(const void* p) {
    uint32_t a;
    asm("{ .reg .u64 t; cvta.to.shared.u64 t, %1; cvt.u32.u64 %0, t; }"
        : "=r"(a) : "l"(p));
    return a;
}

__device__ __forceinline__ void ldsm_x4(uint32_t addr, uint32_t* r) {
    asm volatile("ldmatrix.sync.aligned.m8n8.x4.shared.b16 {%0,%1,%2,%3}, [%4];"
                 : "=r"(r[0]), "=r"(r[1]), "=r"(r[2]), "=r"(r[3]) : "r"(addr));
}

__device__ __forceinline__ void mma_bf16(float* c, const uint32_t* a,
                                         uint32_t b0, uint32_t b1) {
    asm volatile(
        "mma.sync.aligned.m16n8k16.row.col.f32.bf16.bf16.f32 "
        "{%0,%1,%2,%3}, {%4,%5,%6,%7}, {%8,%9}, {%0,%1,%2,%3};"
        : "+f"(c[0]), "+f"(c[1]), "+f"(c[2]), "+f"(c[3])
        : "r"(a[0]), "r"(a[1]), "r"(a[2]), "r"(a[3]), "r"(b0), "r"(b1));
}

// ---------------------------------------------------------------------------
// fp32 -> (bf16 hi, bf16 lo) split conversion, float4-vectorized
// ---------------------------------------------------------------------------
__global__ __launch_bounds__(256)
void conv_split_kernel(const float* __restrict__ src,
                       __nv_bfloat16* __restrict__ hi,
                       __nv_bfloat16* __restrict__ lo, int n4)
{
    int i = blockIdx.x * blockDim.x + threadIdx.x;
    if (i >= n4) return;
    float4 v = ((const float4*)src)[i];
    __nv_bfloat16 h0 = __float2bfloat16(v.x);
    __nv_bfloat16 h1 = __float2bfloat16(v.y);
    __nv_bfloat16 h2 = __float2bfloat16(v.z);
    __nv_bfloat16 h3 = __float2bfloat16(v.w);
    __nv_bfloat16 l0 = __float2bfloat16(v.x - __bfloat162float(h0));
    __nv_bfloat16 l1 = __float2bfloat16(v.y - __bfloat162float(h1));
    __nv_bfloat16 l2 = __float2bfloat16(v.z - __bfloat162float(h2));
    __nv_bfloat16 l3 = __float2bfloat16(v.w - __bfloat162float(h3));
    __nv_bfloat162 ph0 = __nv_bfloat162(h0, h1), ph1 = __nv_bfloat162(h2, h3);
    __nv_bfloat162 pl0 = __nv_bfloat162(l0, l1), pl1 = __nv_bfloat162(l2, l3);
    uint2 uh = make_uint2(*(uint32_t*)&ph0, *(uint32_t*)&ph1);
    uint2 ul = make_uint2(*(uint32_t*)&pl0, *(uint32_t*)&pl1);
    ((uint2*)hi)[i] = uh;
    ((uint2*)lo)[i] = ul;
}

// ---------------------------------------------------------------------------
// Split-bf16 GEMM (NT) on mma.sync tensor cores.
// C[m,n] = sum_k A[m,k]*B[n,k] in fp32-equivalent precision
// (accumulates Ah*Bh + Ah*Bl + Al*Bh into fp32 register accumulators).
//
// CTA tile 128x128, 256 threads (8 warps, 4m x 2n), warp tile 32m x 64n.
// K staged in chunks of 64 bf16 (one 128B SW128 row), double-buffered smem.
// ldmatrix.x4 feeds m16n8k16 bf16 HMMAs.
// ---------------------------------------------------------------------------
#define BKC 64                       // bf16 K elements per stage
#define TILE_BYTES 16384             // 128 rows * 128 B
#define STAGE_BYTES (2 * TILE_BYTES) // A + B
#define GEMM_SMEM (2 * STAGE_BYTES)  // double buffered: 64 KB

// swizzled byte offset of 16B chunk c (0..7) in row r (0..127)
__device__ __forceinline__ uint32_t swz_off(uint32_t r, uint32_t c) {
    return r * 128 + ((c ^ (r & 7)) << 4);
}

__device__ __forceinline__ void gemm_mma_body(
    const __nv_bfloat16* __restrict__ Ah, const __nv_bfloat16* __restrict__ Al,
    const __nv_bfloat16* __restrict__ Bh, const __nv_bfloat16* __restrict__ Bl,
    float* __restrict__ C)
{
    extern __shared__ __align__(128) uint8_t dsm[];
    const uint32_t sb0 = smem_u32(dsm);

    const int tid = threadIdx.x;
    const int lane = tid & 31;
    const int wid = tid >> 5;
    const int wm = (wid >> 1) << 5;   // warp m offset: 0,32,64,96
    const int wn = (wid & 1) << 6;    // warp n offset: 0,64
    const int bm = blockIdx.y << 7;
    const int bn = blockIdx.x << 7;

    float acc[2][8][4];
#pragma unroll
    for (int mf = 0; mf < 2; ++mf)
#pragma unroll
        for (int nf = 0; nf < 8; ++nf)
#pragma unroll
            for (int e = 0; e < 4; ++e) acc[mf][nf][e] = 0.f;

    // loader geometry: 16B chunk id = tid + i*256; row = cid>>3, chunk = cid&7
    const int lrow = tid >> 3;        // base row for i=0 (rows advance by 32)
    const int lch  = tid & 7;

    // precomputed swizzled STS offsets (same for every stage)
    uint32_t sts_off[4];
#pragma unroll
    for (int i = 0; i < 4; ++i)
        sts_off[i] = swz_off(lrow + i * 32, lch);

    // precomputed ldmatrix base offsets (row-dependent part)
    // A frag mf: row = wm + mf*16 + (lane & 15), chunk = ks*2 + (lane>>4)
    // B frag pair p: row = wn + p*16 + ((lane>>4)<<3) + (lane&7),
    //                chunk = ks*2 + ((lane>>3)&1)
    const uint32_t a_row[2] = { (uint32_t)(wm + (lane & 15)),
                                (uint32_t)(wm + 16 + (lane & 15)) };
    const uint32_t a_chb = (uint32_t)(lane >> 4);
    uint32_t b_row[4];
#pragma unroll
    for (int p = 0; p < 4; ++p)
        b_row[p] = (uint32_t)(wn + p * 16 + ((lane >> 4) << 3) + (lane & 7));
    const uint32_t b_chb = (uint32_t)((lane >> 3) & 1);

    uint4 ra[4], rb[4];

#define LDG_STAGE(s_) { \
        const int t_ = (s_) >> 4; \
        const int kc_ = (s_) & 15; \
        const __nv_bfloat16* As_ = (t_ == 2) ? Al : Ah; \
        const __nv_bfloat16* Bs_ = (t_ == 1) ? Bl : Bh; \
        const __nv_bfloat16* ap_ = As_ + (size_t)(bm + lrow) * GD + kc_ * BKC + lch * 8; \
        const __nv_bfloat16* bp_ = Bs_ + (size_t)(bn + lrow) * GD + kc_ * BKC + lch * 8; \
        _Pragma("unroll") \
        for (int i_ = 0; i_ < 4; ++i_) { \
            ra[i_] = *(const uint4*)(ap_ + (size_t)i_ * 32 * GD); \
            rb[i_] = *(const uint4*)(bp_ + (size_t)i_ * 32 * GD); \
        } }

#define STS_STAGE(b_) { \
        const uint32_t ab_ = sb0 + (b_) * STAGE_BYTES; \
        const uint32_t bb_ = ab_ + TILE_BYTES; \
        _Pragma("unroll") \
        for (int i_ = 0; i_ < 4; ++i_) { \
            asm volatile("st.shared.v4.b32 [%0], {%1,%2,%3,%4};" \
                :: "r"(ab_ + sts_off[i_]), "r"(ra[i_].x), "r"(ra[i_].y), \
                   "r"(ra[i_].z), "r"(ra[i_].w) : "memory"); \
            asm volatile("st.shared.v4.b32 [%0], {%1,%2,%3,%4};" \
                :: "r"(bb_ + sts_off[i_]), "r"(rb[i_].x), "r"(rb[i_].y), \
                   "r"(rb[i_].z), "r"(rb[i_].w) : "memory"); \
        } }

    LDG_STAGE(0);
    STS_STAGE(0);
    __syncthreads();

#pragma unroll 1
    for (int s = 0; s < 48; ++s) {
        const uint32_t abase = sb0 + (s & 1) * STAGE_BYTES;
        const uint32_t bbase = abase + TILE_BYTES;

        if (s < 47) LDG_STAGE(s + 1);

#pragma unroll
        for (int ks = 0; ks < 4; ++ks) {
            uint32_t afr[2][4], bfr[4][4];
#pragma unroll
            for (int mf = 0; mf < 2; ++mf)
                ldsm_x4(abase + swz_off(a_row[mf], ks * 2 + a_chb), afr[mf]);
#pragma unroll
            for (int p = 0; p < 4; ++p)
                ldsm_x4(bbase + swz_off(b_row[p], ks * 2 + b_chb), bfr[p]);
#pragma unroll
            for (int mf = 0; mf < 2; ++mf)
#pragma unroll
                for (int nf = 0; nf < 8; ++nf)
                    mma_bf16(acc[mf][nf], afr[mf],
                             bfr[nf >> 1][(nf & 1) * 2],
                             bfr[nf >> 1][(nf & 1) * 2 + 1]);
        }

        if (s < 47) STS_STAGE((s + 1) & 1);
        __syncthreads();
    }
#undef LDG_STAGE
#undef STS_STAGE

    // epilogue: c-frag layout -> rows lane/4 (+8), cols 2*(lane&3) (+1)
    const int cr = lane >> 2;
    const int cc = (lane & 3) << 1;
#pragma unroll
    for (int mf = 0; mf < 2; ++mf) {
        float* r0 = C + (size_t)(bm + wm + mf * 16 + cr) * GD + bn + wn + cc;
        float* r1 = r0 + 8 * GD;
#pragma unroll
        for (int nf = 0; nf < 8; ++nf) {
            *(float2*)(r0 + nf * 8) = make_float2(acc[mf][nf][0], acc[mf][nf][1]);
            *(float2*)(r1 + nf * 8) = make_float2(acc[mf][nf][2], acc[mf][nf][3]);
        }
    }
}

// z = 0 -> K, 1 -> Q, 2 -> V
__global__ __launch_bounds__(256)
void qkv_mma_kernel()
{
    if (blockIdx.z == 0)      gemm_mma_body(g_xh, g_xl, g_Wkh, g_Wkl, g_K);
    else if (blockIdx.z == 1) gemm_mma_body(g_xh, g_xl, g_Wqh, g_Wql, g_Q);
    else                      gemm_mma_body(g_xh, g_xl, g_Wvh, g_Wvl, g_V);
}

__global__ __launch_bounds__(256)
void oproj_mma_kernel(float* __restrict__ out)
{
    gemm_mma_body(g_aoh, g_aol, g_Woh, g_Wol, out);
}

// ---------------------------------------------------------------------------
// Fast exp (FMA-only, for x <= 0; tolerant of -1e30 sentinels)
// ---------------------------------------------------------------------------
__device__ __forceinline__ float fexp(float x) {
    float y = fmaxf(x * 1.4426950408889634f, -126.0f);
    float r = y + 12582912.0f;
    int   n = __float_as_int(r) - 0x4B400000;
    float k = y - (r - 12582912.0f);
    float p = 1.3333558146428443e-3f;
    p = fmaf(p, k, 9.618129107628477e-3f);
    p = fmaf(p, k, 5.550410866482158e-2f);
    p = fmaf(p, k, 2.402265069591007e-1f);
    p = fmaf(p, k, 6.931471805599453e-1f);
    p = fmaf(p, k, 1.0f);
    return p * __int_as_float((n + 127) << 23);
}

// ---------------------------------------------------------------------------
// Flash-style causal attention, fp32 (unchanged, known-passing).
// ---------------------------------------------------------------------------
#define SWZ(rr, cc) (((cc) * 64) + ((((rr) >> 2) ^ ((cc) & 15)) << 2) + ((rr) & 3))

__global__ __launch_bounds__(256)
void flash_kernel()
{
    __shared__ float Qt[64 * 64];
    __shared__ float Kt[64 * 64];   // reused as Pt
    __shared__ float Vs[64 * 64];

    const int tid = threadIdx.x;
    const int tx = tid & 15;
    const int ty = tid >> 4;
    const int qt = blockIdx.x;
    const int bh = blockIdx.y;
    const int b = bh >> 4, h = bh & 15;

    const int base = b * GT * GD + h * HD;
    const float* qg = g_Q + base + qt * 64 * GD;

#pragma unroll
    for (int it = 0; it < 4; ++it) {
        int i = tid + it * 256;
        int r = i >> 4;
        int c4 = (i & 15) << 2;
        float4 v = *(const float4*)(qg + r * GD + c4);
        Qt[SWZ(r, c4 + 0)] = v.x;
        Qt[SWZ(r, c4 + 1)] = v.y;
        Qt[SWZ(r, c4 + 2)] = v.z;
        Qt[SWZ(r, c4 + 3)] = v.w;
    }

    float m[4], l[4], o[4][4];
#pragma unroll
    for (int i = 0; i < 4; ++i) {
        m[i] = -1e30f;
        l[i] = 0.f;
#pragma unroll
        for (int j = 0; j < 4; ++j) o[i][j] = 0.f;
    }

    const int r0 = ty << 2;
    const int c0 = tx << 2;

    for (int jt = 0; jt <= qt; ++jt) {
        const float* kg = g_K + base + jt * 64 * GD;
        const float* vg = g_V + base + jt * 64 * GD;

        __syncthreads();

#pragma unroll
        for (int it = 0; it < 4; ++it) {
            int i = tid + it * 256;
            int r = i >> 4;
            int c4 = (i & 15) << 2;
            float4 kv = *(const float4*)(kg + r * GD + c4);
            Kt[SWZ(r, c4 + 0)] = kv.x;
            Kt[SWZ(r, c4 + 1)] = kv.y;
            Kt[SWZ(r, c4 + 2)] = kv.z;
            Kt[SWZ(r, c4 + 3)] = kv.w;
            float4 vv = *(const float4*)(vg + r * GD + c4);
            *(float4*)&Vs[r * 64 + c4] = vv;
        }
        __syncthreads();

        float s[4][4];
#pragma unroll
        for (int i = 0; i < 4; ++i)
#pragma unroll
            for (int j = 0; j < 4; ++j) s[i][j] = 0.f;

#pragma unroll 16
        for (int hh = 0; hh < 64; ++hh) {
            const int sw = hh & 15;
            float4 qa = *(const float4*)&Qt[hh * 64 + ((ty ^ sw) << 2)];
            float4 kb = *(const float4*)&Kt[hh * 64 + ((tx ^ sw) << 2)];
            float ar[4] = {qa.x, qa.y, qa.z, qa.w};
            float br[4] = {kb.x, kb.y, kb.z, kb.w};
#pragma unroll
            for (int i = 0; i < 4; ++i)
#pragma unroll
                for (int j = 0; j < 4; ++j)
                    s[i][j] = fmaf(ar[i], br[j], s[i][j]);
        }

        const bool diag = (jt == qt);
#pragma unroll
        for (int i = 0; i < 4; ++i)
#pragma unroll
            for (int j = 0; j < 4; ++j) {
                float v = s[i][j] * 0.125f;
                if (diag && (c0 + j) > (r0 + i)) v = -1e30f;
                s[i][j] = v;
            }

#pragma unroll
        for (int i = 0; i < 4; ++i) {
            float rm = fmaxf(fmaxf(s[i][0], s[i][1]), fmaxf(s[i][2], s[i][3]));
            rm = fmaxf(rm, __shfl_xor_sync(0xffffffffu, rm, 1));
            rm = fmaxf(rm, __shfl_xor_sync(0xffffffffu, rm, 2));
            rm = fmaxf(rm, __shfl_xor_sync(0xffffffffu, rm, 4));
            rm = fmaxf(rm, __shfl_xor_sync(0xffffffffu, rm, 8));
            float mn = fmaxf(m[i], rm);
            float alpha = fexp(m[i] - mn);
            float rs = 0.f;
#pragma unroll
            for (int j = 0; j < 4; ++j) {
                float p = fexp(s[i][j] - mn);
                s[i][j] = p;
                rs += p;
            }
            rs += __shfl_xor_sync(0xffffffffu, rs, 1);
            rs += __shfl_xor_sync(0xffffffffu, rs, 2);
            rs += __shfl_xor_sync(0xffffffffu, rs, 4);
            rs += __shfl_xor_sync(0xffffffffu, rs, 8);
            l[i] = l[i] * alpha + rs;
            m[i] = mn;
#pragma unroll
            for (int j = 0; j < 4; ++j) o[i][j] *= alpha;
        }

        __syncthreads();

#pragma unroll
        for (int i = 0; i < 4; ++i)
#pragma unroll
            for (int j = 0; j < 4; ++j) {
                int c = c0 + j;
                Kt[c * 64 + ((ty ^ (c & 15)) << 2) + i] = s[i][j];
            }
        __syncthreads();

#pragma unroll 8
        for (int c = 0; c < 64; ++c) {
            float4 pa = *(const float4*)&Kt[c * 64 + ((ty ^ (c & 15)) << 2)];
            float4 vb = *(const float4*)&Vs[c * 64 + (tx << 2)];
            float ar[4] = {pa.x, pa.y, pa.z, pa.w};
            float br[4] = {vb.x, vb.y, vb.z, vb.w};
#pragma unroll
            for (int i = 0; i < 4; ++i)
#pragma unroll
                for (int j = 0; j < 4; ++j)
                    o[i][j] = fmaf(ar[i], br[j], o[i][j]);
        }
    }

    float* og = g_AO + base + qt * 64 * GD;
#pragma unroll
    for (int i = 0; i < 4; ++i) {
        float inv = 1.0f / l[i];
        float4 w = make_float4(o[i][0] * inv, o[i][1] * inv,
                               o[i][2] * inv, o[i][3] * inv);
        *(float4*)(og + (r0 + i) * GD + (tx << 2)) = w;
    }
}

// ---------------------------------------------------------------------------
// Launch sequence (graph-capturable, allocation-free).
// Inputs: x, Wk, Wq, Wv, Wo.
// ---------------------------------------------------------------------------
extern "C" void kernel_launch(void* const* d_in, const int* in_sizes, int n_in,
                              void* d_out, int out_size)
{
    const float* x  = (const float*)d_in[0];
    const float* Wk = (const float*)d_in[1];
    const float* Wq = (const float*)d_in[2];
    const float* Wv = (const float*)d_in[3];
    const float* Wo = (const float*)d_in[4];
    float* out = (float*)d_out;
    (void)in_sizes; (void)n_in; (void)out_size;

    static bool attr_done = false;
    if (!attr_done) {
        cudaFuncSetAttribute(qkv_mma_kernel,
                             cudaFuncAttributeMaxDynamicSharedMemorySize, GEMM_SMEM);
        cudaFuncSetAttribute(oproj_mma_kernel,
                             cudaFuncAttributeMaxDynamicSharedMemorySize, GEMM_SMEM);
        attr_done = true;
    }

    // resolve device-symbol addresses for conversion targets (host API, no alloc)
    __nv_bfloat16 *xh, *xl, *aoh, *aol;
    __nv_bfloat16 *wkh, *wkl, *wqh, *wql, *wvh, *wvl, *woh, *wol;
    float *ao;
    cudaGetSymbolAddress((void**)&xh,  g_xh);
    cudaGetSymbolAddress((void**)&xl,  g_xl);
    cudaGetSymbolAddress((void**)&aoh, g_aoh);
    cudaGetSymbolAddress((void**)&aol, g_aol);
    cudaGetSymbolAddress((void**)&wkh, g_Wkh);
    cudaGetSymbolAddress((void**)&wkl, g_Wkl);
    cudaGetSymbolAddress((void**)&wqh, g_Wqh);
    cudaGetSymbolAddress((void**)&wql, g_Wql);
    cudaGetSymbolAddress((void**)&wvh, g_Wvh);
    cudaGetSymbolAddress((void**)&wvl, g_Wvl);
    cudaGetSymbolAddress((void**)&woh, g_Woh);
    cudaGetSymbolAddress((void**)&wol, g_Wol);
    cudaGetSymbolAddress((void**)&ao,  g_AO);

    const int n4x = GM * GD / 4;   // 2,097,152
    const int n4w = GD * GD / 4;   // 262,144

    conv_split_kernel<<<n4x / 256, 256>>>(x, xh, xl, n4x);
    conv_split_kernel<<<n4w / 256, 256>>>(Wk, wkh, wkl, n4w);
    conv_split_kernel<<<n4w / 256, 256>>>(Wq, wqh, wql, n4w);
    conv_split_kernel<<<n4w / 256, 256>>>(Wv, wvh, wvl, n4w);
    conv_split_kernel<<<n4w / 256, 256>>>(Wo, woh, wol, n4w);

    qkv_mma_kernel<<<dim3(GD / 128, GM / 128, 3), 256, GEMM_SMEM>>>();

    flash_kernel<<<dim3(GT / 64, GB * NHEAD), 256>>>();

    conv_split_kernel<<<n4x / 256, 256>>>(ao, aoh, aol, n4x);
    oproj_mma_kernel<<<dim3(GD / 128, GM / 128), 256, GEMM_SMEM>>>(out);
}

// round 4
// speedup vs baseline: 1.7078x; 1.0000x over previous
#include <cuda_runtime.h>
#include <cuda_bf16.h>
#include <cstdint>

// Problem constants (fixed: B=8, T=1024, D=1024, 16 heads)
#define GB 8
#define GT 1024
#define GD 1024
#define NHEAD 16
#define HD 64
#define GM (GB * GT)   // 8192 rows

// ---------------------------------------------------------------------------
// Device scratch (no allocations allowed)
// ---------------------------------------------------------------------------
__device__ float g_Q[GM * GD];
__device__ float g_K[GM * GD];
__device__ float g_V[GM * GD];
__device__ float g_AO[GM * GD];

__device__ __nv_bfloat16 g_xh[GM * GD];
__device__ __nv_bfloat16 g_xl[GM * GD];
__device__ __nv_bfloat16 g_aoh[GM * GD];
__device__ __nv_bfloat16 g_aol[GM * GD];
__device__ __nv_bfloat16 g_Wkh[GD * GD], g_Wkl[GD * GD];
__device__ __nv_bfloat16 g_Wqh[GD * GD], g_Wql[GD * GD];
__device__ __nv_bfloat16 g_Wvh[GD * GD], g_Wvl[GD * GD];
__device__ __nv_bfloat16 g_Woh[GD * GD], g_Wol[GD * GD];

// ---------------------------------------------------------------------------
// Helpers
// ---------------------------------------------------------------------------
__device__ __forceinline__ uint32_t smem_u32(const void* p) {
    uint32_t a;
    asm("{ .reg .u64 t; cvta.to.shared.u64 t, %1; cvt.u32.u64 %0, t; }"
        : "=r"(a) : "l"(p));
    return a;
}

__device__ __forceinline__ void ldsm_x4(uint32_t addr, uint32_t* r) {
    asm volatile("ldmatrix.sync.aligned.m8n8.x4.shared.b16 {%0,%1,%2,%3}, [%4];"
                 : "=r"(r[0]), "=r"(r[1]), "=r"(r[2]), "=r"(r[3]) : "r"(addr));
}

__device__ __forceinline__ void mma_bf16(float* c, const uint32_t* a,
                                         uint32_t b0, uint32_t b1) {
    asm volatile(
        "mma.sync.aligned.m16n8k16.row.col.f32.bf16.bf16.f32 "
        "{%0,%1,%2,%3}, {%4,%5,%6,%7}, {%8,%9}, {%0,%1,%2,%3};"
        : "+f"(c[0]), "+f"(c[1]), "+f"(c[2]), "+f"(c[3])
        : "r"(a[0]), "r"(a[1]), "r"(a[2]), "r"(a[3]), "r"(b0), "r"(b1));
}

// ---------------------------------------------------------------------------
// fp32 -> (bf16 hi, bf16 lo) split conversion, float4-vectorized
// ---------------------------------------------------------------------------
__global__ __launch_bounds__(256)
void conv_split_kernel(const float* __restrict__ src,
                       __nv_bfloat16* __restrict__ hi,
                       __nv_bfloat16* __restrict__ lo, int n4)
{
    int i = blockIdx.x * blockDim.x + threadIdx.x;
    if (i >= n4) return;
    float4 v = ((const float4*)src)[i];
    __nv_bfloat16 h0 = __float2bfloat16(v.x);
    __nv_bfloat16 h1 = __float2bfloat16(v.y);
    __nv_bfloat16 h2 = __float2bfloat16(v.z);
    __nv_bfloat16 h3 = __float2bfloat16(v.w);
    __nv_bfloat16 l0 = __float2bfloat16(v.x - __bfloat162float(h0));
    __nv_bfloat16 l1 = __float2bfloat16(v.y - __bfloat162float(h1));
    __nv_bfloat16 l2 = __float2bfloat16(v.z - __bfloat162float(h2));
    __nv_bfloat16 l3 = __float2bfloat16(v.w - __bfloat162float(h3));
    __nv_bfloat162 ph0 = __nv_bfloat162(h0, h1), ph1 = __nv_bfloat162(h2, h3);
    __nv_bfloat162 pl0 = __nv_bfloat162(l0, l1), pl1 = __nv_bfloat162(l2, l3);
    uint2 uh = make_uint2(*(uint32_t*)&ph0, *(uint32_t*)&ph1);
    uint2 ul = make_uint2(*(uint32_t*)&pl0, *(uint32_t*)&pl1);
    ((uint2*)hi)[i] = uh;
    ((uint2*)lo)[i] = ul;
}

// ---------------------------------------------------------------------------
// Split-bf16 GEMM (NT) on mma.sync tensor cores.
// C[m,n] = sum_k A[m,k]*B[n,k] in fp32-equivalent precision
// (accumulates Ah*Bh + Ah*Bl + Al*Bh into fp32 register accumulators).
//
// CTA tile 128x128, 256 threads (8 warps, 4m x 2n), warp tile 32m x 64n.
// K staged in chunks of 64 bf16 (one 128B SW128 row), double-buffered smem.
// ldmatrix.x4 feeds m16n8k16 bf16 HMMAs.
// ---------------------------------------------------------------------------
#define BKC 64                       // bf16 K elements per stage
#define TILE_BYTES 16384             // 128 rows * 128 B
#define STAGE_BYTES (2 * TILE_BYTES) // A + B
#define GEMM_SMEM (2 * STAGE_BYTES)  // double buffered: 64 KB

// swizzled byte offset of 16B chunk c (0..7) in row r (0..127)
__device__ __forceinline__ uint32_t swz_off(uint32_t r, uint32_t c) {
    return r * 128 + ((c ^ (r & 7)) << 4);
}

__device__ __forceinline__ void gemm_mma_body(
    const __nv_bfloat16* __restrict__ Ah, const __nv_bfloat16* __restrict__ Al,
    const __nv_bfloat16* __restrict__ Bh, const __nv_bfloat16* __restrict__ Bl,
    float* __restrict__ C)
{
    extern __shared__ __align__(128) uint8_t dsm[];
    const uint32_t sb0 = smem_u32(dsm);

    const int tid = threadIdx.x;
    const int lane = tid & 31;
    const int wid = tid >> 5;
    const int wm = (wid >> 1) << 5;   // warp m offset: 0,32,64,96
    const int wn = (wid & 1) << 6;    // warp n offset: 0,64
    const int bm = blockIdx.y << 7;
    const int bn = blockIdx.x << 7;

    float acc[2][8][4];
#pragma unroll
    for (int mf = 0; mf < 2; ++mf)
#pragma unroll
        for (int nf = 0; nf < 8; ++nf)
#pragma unroll
            for (int e = 0; e < 4; ++e) acc[mf][nf][e] = 0.f;

    // loader geometry: 16B chunk id = tid + i*256; row = cid>>3, chunk = cid&7
    const int lrow = tid >> 3;        // base row for i=0 (rows advance by 32)
    const int lch  = tid & 7;

    // precomputed swizzled STS offsets (same for every stage)
    uint32_t sts_off[4];
#pragma unroll
    for (int i = 0; i < 4; ++i)
        sts_off[i] = swz_off(lrow + i * 32, lch);

    // precomputed ldmatrix base offsets (row-dependent part)
    // A frag mf: row = wm + mf*16 + (lane & 15), chunk = ks*2 + (lane>>4)
    // B frag pair p: row = wn + p*16 + ((lane>>4)<<3) + (lane&7),
    //                chunk = ks*2 + ((lane>>3)&1)
    const uint32_t a_row[2] = { (uint32_t)(wm + (lane & 15)),
                                (uint32_t)(wm + 16 + (lane & 15)) };
    const uint32_t a_chb = (uint32_t)(lane >> 4);
    uint32_t b_row[4];
#pragma unroll
    for (int p = 0; p < 4; ++p)
        b_row[p] = (uint32_t)(wn + p * 16 + ((lane >> 4) << 3) + (lane & 7));
    const uint32_t b_chb = (uint32_t)((lane >> 3) & 1);

    uint4 ra[4], rb[4];

#define LDG_STAGE(s_) { \
        const int t_ = (s_) >> 4; \
        const int kc_ = (s_) & 15; \
        const __nv_bfloat16* As_ = (t_ == 2) ? Al : Ah; \
        const __nv_bfloat16* Bs_ = (t_ == 1) ? Bl : Bh; \
        const __nv_bfloat16* ap_ = As_ + (size_t)(bm + lrow) * GD + kc_ * BKC + lch * 8; \
        const __nv_bfloat16* bp_ = Bs_ + (size_t)(bn + lrow) * GD + kc_ * BKC + lch * 8; \
        _Pragma("unroll") \
        for (int i_ = 0; i_ < 4; ++i_) { \
            ra[i_] = *(const uint4*)(ap_ + (size_t)i_ * 32 * GD); \
            rb[i_] = *(const uint4*)(bp_ + (size_t)i_ * 32 * GD); \
        } }

#define STS_STAGE(b_) { \
        const uint32_t ab_ = sb0 + (b_) * STAGE_BYTES; \
        const uint32_t bb_ = ab_ + TILE_BYTES; \
        _Pragma("unroll") \
        for (int i_ = 0; i_ < 4; ++i_) { \
            asm volatile("st.shared.v4.b32 [%0], {%1,%2,%3,%4};" \
                :: "r"(ab_ + sts_off[i_]), "r"(ra[i_].x), "r"(ra[i_].y), \
                   "r"(ra[i_].z), "r"(ra[i_].w) : "memory"); \
            asm volatile("st.shared.v4.b32 [%0], {%1,%2,%3,%4};" \
                :: "r"(bb_ + sts_off[i_]), "r"(rb[i_].x), "r"(rb[i_].y), \
                   "r"(rb[i_].z), "r"(rb[i_].w) : "memory"); \
        } }

    LDG_STAGE(0);
    STS_STAGE(0);
    __syncthreads();

#pragma unroll 1
    for (int s = 0; s < 48; ++s) {
        const uint32_t abase = sb0 + (s & 1) * STAGE_BYTES;
        const uint32_t bbase = abase + TILE_BYTES;

        if (s < 47) LDG_STAGE(s + 1);

#pragma unroll
        for (int ks = 0; ks < 4; ++ks) {
            uint32_t afr[2][4], bfr[4][4];
#pragma unroll
            for (int mf = 0; mf < 2; ++mf)
                ldsm_x4(abase + swz_off(a_row[mf], ks * 2 + a_chb), afr[mf]);
#pragma unroll
            for (int p = 0; p < 4; ++p)
                ldsm_x4(bbase + swz_off(b_row[p], ks * 2 + b_chb), bfr[p]);
#pragma unroll
            for (int mf = 0; mf < 2; ++mf)
#pragma unroll
                for (int nf = 0; nf < 8; ++nf)
                    mma_bf16(acc[mf][nf], afr[mf],
                             bfr[nf >> 1][(nf & 1) * 2],
                             bfr[nf >> 1][(nf & 1) * 2 + 1]);
        }

        if (s < 47) STS_STAGE((s + 1) & 1);
        __syncthreads();
    }
#undef LDG_STAGE
#undef STS_STAGE

    // epilogue: c-frag layout -> rows lane/4 (+8), cols 2*(lane&3) (+1)
    const int cr = lane >> 2;
    const int cc = (lane & 3) << 1;
#pragma unroll
    for (int mf = 0; mf < 2; ++mf) {
        float* r0 = C + (size_t)(bm + wm + mf * 16 + cr) * GD + bn + wn + cc;
        float* r1 = r0 + 8 * GD;
#pragma unroll
        for (int nf = 0; nf < 8; ++nf) {
            *(float2*)(r0 + nf * 8) = make_float2(acc[mf][nf][0], acc[mf][nf][1]);
            *(float2*)(r1 + nf * 8) = make_float2(acc[mf][nf][2], acc[mf][nf][3]);
        }
    }
}

// z = 0 -> K, 1 -> Q, 2 -> V
__global__ __launch_bounds__(256)
void qkv_mma_kernel()
{
    if (blockIdx.z == 0)      gemm_mma_body(g_xh, g_xl, g_Wkh, g_Wkl, g_K);
    else if (blockIdx.z == 1) gemm_mma_body(g_xh, g_xl, g_Wqh, g_Wql, g_Q);
    else                      gemm_mma_body(g_xh, g_xl, g_Wvh, g_Wvl, g_V);
}

__global__ __launch_bounds__(256)
void oproj_mma_kernel(float* __restrict__ out)
{
    gemm_mma_body(g_aoh, g_aol, g_Woh, g_Wol, out);
}

// ---------------------------------------------------------------------------
// Fast exp (FMA-only, for x <= 0; tolerant of -1e30 sentinels)
// ---------------------------------------------------------------------------
__device__ __forceinline__ float fexp(float x) {
    float y = fmaxf(x * 1.4426950408889634f, -126.0f);
    float r = y + 12582912.0f;
    int   n = __float_as_int(r) - 0x4B400000;
    float k = y - (r - 12582912.0f);
    float p = 1.3333558146428443e-3f;
    p = fmaf(p, k, 9.618129107628477e-3f);
    p = fmaf(p, k, 5.550410866482158e-2f);
    p = fmaf(p, k, 2.402265069591007e-1f);
    p = fmaf(p, k, 6.931471805599453e-1f);
    p = fmaf(p, k, 1.0f);
    return p * __int_as_float((n + 127) << 23);
}

// ---------------------------------------------------------------------------
// Flash-style causal attention, fp32 (unchanged, known-passing).
// ---------------------------------------------------------------------------
#define SWZ(rr, cc) (((cc) * 64) + ((((rr) >> 2) ^ ((cc) & 15)) << 2) + ((rr) & 3))

__global__ __launch_bounds__(256)
void flash_kernel()
{
    __shared__ float Qt[64 * 64];
    __shared__ float Kt[64 * 64];   // reused as Pt
    __shared__ float Vs[64 * 64];

    const int tid = threadIdx.x;
    const int tx = tid & 15;
    const int ty = tid >> 4;
    const int qt = blockIdx.x;
    const int bh = blockIdx.y;
    const int b = bh >> 4, h = bh & 15;

    const int base = b * GT * GD + h * HD;
    const float* qg = g_Q + base + qt * 64 * GD;

#pragma unroll
    for (int it = 0; it < 4; ++it) {
        int i = tid + it * 256;
        int r = i >> 4;
        int c4 = (i & 15) << 2;
        float4 v = *(const float4*)(qg + r * GD + c4);
        Qt[SWZ(r, c4 + 0)] = v.x;
        Qt[SWZ(r, c4 + 1)] = v.y;
        Qt[SWZ(r, c4 + 2)] = v.z;
        Qt[SWZ(r, c4 + 3)] = v.w;
    }

    float m[4], l[4], o[4][4];
#pragma unroll
    for (int i = 0; i < 4; ++i) {
        m[i] = -1e30f;
        l[i] = 0.f;
#pragma unroll
        for (int j = 0; j < 4; ++j) o[i][j] = 0.f;
    }

    const int r0 = ty << 2;
    const int c0 = tx << 2;

    for (int jt = 0; jt <= qt; ++jt) {
        const float* kg = g_K + base + jt * 64 * GD;
        const float* vg = g_V + base + jt * 64 * GD;

        __syncthreads();

#pragma unroll
        for (int it = 0; it < 4; ++it) {
            int i = tid + it * 256;
            int r = i >> 4;
            int c4 = (i & 15) << 2;
            float4 kv = *(const float4*)(kg + r * GD + c4);
            Kt[SWZ(r, c4 + 0)] = kv.x;
            Kt[SWZ(r, c4 + 1)] = kv.y;
            Kt[SWZ(r, c4 + 2)] = kv.z;
            Kt[SWZ(r, c4 + 3)] = kv.w;
            float4 vv = *(const float4*)(vg + r * GD + c4);
            *(float4*)&Vs[r * 64 + c4] = vv;
        }
        __syncthreads();

        float s[4][4];
#pragma unroll
        for (int i = 0; i < 4; ++i)
#pragma unroll
            for (int j = 0; j < 4; ++j) s[i][j] = 0.f;

#pragma unroll 16
        for (int hh = 0; hh < 64; ++hh) {
            const int sw = hh & 15;
            float4 qa = *(const float4*)&Qt[hh * 64 + ((ty ^ sw) << 2)];
            float4 kb = *(const float4*)&Kt[hh * 64 + ((tx ^ sw) << 2)];
            float ar[4] = {qa.x, qa.y, qa.z, qa.w};
            float br[4] = {kb.x, kb.y, kb.z, kb.w};
#pragma unroll
            for (int i = 0; i < 4; ++i)
#pragma unroll
                for (int j = 0; j < 4; ++j)
                    s[i][j] = fmaf(ar[i], br[j], s[i][j]);
        }

        const bool diag = (jt == qt);
#pragma unroll
        for (int i = 0; i < 4; ++i)
#pragma unroll
            for (int j = 0; j < 4; ++j) {
                float v = s[i][j] * 0.125f;
                if (diag && (c0 + j) > (r0 + i)) v = -1e30f;
                s[i][j] = v;
            }

#pragma unroll
        for (int i = 0; i < 4; ++i) {
            float rm = fmaxf(fmaxf(s[i][0], s[i][1]), fmaxf(s[i][2], s[i][3]));
            rm = fmaxf(rm, __shfl_xor_sync(0xffffffffu, rm, 1));
            rm = fmaxf(rm, __shfl_xor_sync(0xffffffffu, rm, 2));
            rm = fmaxf(rm, __shfl_xor_sync(0xffffffffu, rm, 4));
            rm = fmaxf(rm, __shfl_xor_sync(0xffffffffu, rm, 8));
            float mn = fmaxf(m[i], rm);
            float alpha = fexp(m[i] - mn);
            float rs = 0.f;
#pragma unroll
            for (int j = 0; j < 4; ++j) {
                float p = fexp(s[i][j] - mn);
                s[i][j] = p;
                rs += p;
            }
            rs += __shfl_xor_sync(0xffffffffu, rs, 1);
            rs += __shfl_xor_sync(0xffffffffu, rs, 2);
            rs += __shfl_xor_sync(0xffffffffu, rs, 4);
            rs += __shfl_xor_sync(0xffffffffu, rs, 8);
            l[i] = l[i] * alpha + rs;
            m[i] = mn;
#pragma unroll
            for (int j = 0; j < 4; ++j) o[i][j] *= alpha;
        }

        __syncthreads();

#pragma unroll
        for (int i = 0; i < 4; ++i)
#pragma unroll
            for (int j = 0; j < 4; ++j) {
                int c = c0 + j;
                Kt[c * 64 + ((ty ^ (c & 15)) << 2) + i] = s[i][j];
            }
        __syncthreads();

#pragma unroll 8
        for (int c = 0; c < 64; ++c) {
            float4 pa = *(const float4*)&Kt[c * 64 + ((ty ^ (c & 15)) << 2)];
            float4 vb = *(const float4*)&Vs[c * 64 + (tx << 2)];
            float ar[4] = {pa.x, pa.y, pa.z, pa.w};
            float br[4] = {vb.x, vb.y, vb.z, vb.w};
#pragma unroll
            for (int i = 0; i < 4; ++i)
#pragma unroll
                for (int j = 0; j < 4; ++j)
                    o[i][j] = fmaf(ar[i], br[j], o[i][j]);
        }
    }

    float* og = g_AO + base + qt * 64 * GD;
#pragma unroll
    for (int i = 0; i < 4; ++i) {
        float inv = 1.0f / l[i];
        float4 w = make_float4(o[i][0] * inv, o[i][1] * inv,
                               o[i][2] * inv, o[i][3] * inv);
        *(float4*)(og + (r0 + i) * GD + (tx << 2)) = w;
    }
}

// ---------------------------------------------------------------------------
// Launch sequence (graph-capturable, allocation-free).
// Inputs: x, Wk, Wq, Wv, Wo.
// ---------------------------------------------------------------------------
extern "C" void kernel_launch(void* const* d_in, const int* in_sizes, int n_in,
                              void* d_out, int out_size)
{
    const float* x  = (const float*)d_in[0];
    const float* Wk = (const float*)d_in[1];
    const float* Wq = (const float*)d_in[2];
    const float* Wv = (const float*)d_in[3];
    const float* Wo = (const float*)d_in[4];
    float* out = (float*)d_out;
    (void)in_sizes; (void)n_in; (void)out_size;

    static bool attr_done = false;
    if (!attr_done) {
        cudaFuncSetAttribute(qkv_mma_kernel,
                             cudaFuncAttributeMaxDynamicSharedMemorySize, GEMM_SMEM);
        cudaFuncSetAttribute(oproj_mma_kernel,
                             cudaFuncAttributeMaxDynamicSharedMemorySize, GEMM_SMEM);
        attr_done = true;
    }

    // resolve device-symbol addresses for conversion targets (host API, no alloc)
    __nv_bfloat16 *xh, *xl, *aoh, *aol;
    __nv_bfloat16 *wkh, *wkl, *wqh, *wql, *wvh, *wvl, *woh, *wol;
    float *ao;
    cudaGetSymbolAddress((void**)&xh,  g_xh);
    cudaGetSymbolAddress((void**)&xl,  g_xl);
    cudaGetSymbolAddress((void**)&aoh, g_aoh);
    cudaGetSymbolAddress((void**)&aol, g_aol);
    cudaGetSymbolAddress((void**)&wkh, g_Wkh);
    cudaGetSymbolAddress((void**)&wkl, g_Wkl);
    cudaGetSymbolAddress((void**)&wqh, g_Wqh);
    cudaGetSymbolAddress((void**)&wql, g_Wql);
    cudaGetSymbolAddress((void**)&wvh, g_Wvh);
    cudaGetSymbolAddress((void**)&wvl, g_Wvl);
    cudaGetSymbolAddress((void**)&woh, g_Woh);
    cudaGetSymbolAddress((void**)&wol, g_Wol);
    cudaGetSymbolAddress((void**)&ao,  g_AO);

    const int n4x = GM * GD / 4;   // 2,097,152
    const int n4w = GD * GD / 4;   // 262,144

    conv_split_kernel<<<n4x / 256, 256>>>(x, xh, xl, n4x);
    conv_split_kernel<<<n4w / 256, 256>>>(Wk, wkh, wkl, n4w);
    conv_split_kernel<<<n4w / 256, 256>>>(Wq, wqh, wql, n4w);
    conv_split_kernel<<<n4w / 256, 256>>>(Wv, wvh, wvl, n4w);
    conv_split_kernel<<<n4w / 256, 256>>>(Wo, woh, wol, n4w);

    qkv_mma_kernel<<<dim3(GD / 128, GM / 128, 3), 256, GEMM_SMEM>>>();

    flash_kernel<<<dim3(GT / 64, GB * NHEAD), 256>>>();

    conv_split_kernel<<<n4x / 256, 256>>>(ao, aoh, aol, n4x);
    oproj_mma_kernel<<<dim3(GD / 128, GM / 128), 256, GEMM_SMEM>>>(out);
}

// round 5
// speedup vs baseline: 1.7154x; 1.0044x over previous
#include <cuda_runtime.h>
#include <cuda_bf16.h>
#include <cstdint>

// Problem constants (fixed: B=8, T=1024, D=1024, 16 heads)
#define GB 8
#define GT 1024
#define GD 1024
#define NHEAD 16
#define HD 64
#define GM (GB * GT)   // 8192 rows

// ---------------------------------------------------------------------------
// Device scratch (no allocations allowed)
// ---------------------------------------------------------------------------
__device__ float g_Q[GM * GD];
__device__ float g_K[GM * GD];
__device__ float g_V[GM * GD];
__device__ float g_AO[GM * GD];

__device__ __nv_bfloat16 g_xh[GM * GD];
__device__ __nv_bfloat16 g_xl[GM * GD];
__device__ __nv_bfloat16 g_aoh[GM * GD];
__device__ __nv_bfloat16 g_aol[GM * GD];
__device__ __nv_bfloat16 g_Wkh[GD * GD], g_Wkl[GD * GD];
__device__ __nv_bfloat16 g_Wqh[GD * GD], g_Wql[GD * GD];
__device__ __nv_bfloat16 g_Wvh[GD * GD], g_Wvl[GD * GD];
__device__ __nv_bfloat16 g_Woh[GD * GD], g_Wol[GD * GD];

// ---------------------------------------------------------------------------
// Helpers
// ---------------------------------------------------------------------------
__device__ __forceinline__ uint32_t smem_u32(const void* p) {
    uint32_t a;
    asm("{ .reg .u64 t; cvta.to.shared.u64 t, %1; cvt.u32.u64 %0, t; }"
        : "=r"(a) : "l"(p));
    return a;
}

__device__ __forceinline__ void ldsm_x4(uint32_t addr, uint32_t* r) {
    asm volatile("ldmatrix.sync.aligned.m8n8.x4.shared.b16 {%0,%1,%2,%3}, [%4];"
                 : "=r"(r[0]), "=r"(r[1]), "=r"(r[2]), "=r"(r[3]) : "r"(addr));
}

__device__ __forceinline__ void mma_bf16(float* c, const uint32_t* a,
                                         uint32_t b0, uint32_t b1) {
    asm volatile(
        "mma.sync.aligned.m16n8k16.row.col.f32.bf16.bf16.f32 "
        "{%0,%1,%2,%3}, {%4,%5,%6,%7}, {%8,%9}, {%0,%1,%2,%3};"
        : "+f"(c[0]), "+f"(c[1]), "+f"(c[2]), "+f"(c[3])
        : "r"(a[0]), "r"(a[1]), "r"(a[2]), "r"(a[3]), "r"(b0), "r"(b1));
}

// ---------------------------------------------------------------------------
// fp32 -> (bf16 hi, bf16 lo) split conversion, float4-vectorized
// ---------------------------------------------------------------------------
__global__ __launch_bounds__(256)
void conv_split_kernel(const float* __restrict__ src,
                       __nv_bfloat16* __restrict__ hi,
                       __nv_bfloat16* __restrict__ lo, int n4)
{
    int i = blockIdx.x * blockDim.x + threadIdx.x;
    if (i >= n4) return;
    float4 v = ((const float4*)src)[i];
    __nv_bfloat16 h0 = __float2bfloat16(v.x);
    __nv_bfloat16 h1 = __float2bfloat16(v.y);
    __nv_bfloat16 h2 = __float2bfloat16(v.z);
    __nv_bfloat16 h3 = __float2bfloat16(v.w);
    __nv_bfloat16 l0 = __float2bfloat16(v.x - __bfloat162float(h0));
    __nv_bfloat16 l1 = __float2bfloat16(v.y - __bfloat162float(h1));
    __nv_bfloat16 l2 = __float2bfloat16(v.z - __bfloat162float(h2));
    __nv_bfloat16 l3 = __float2bfloat16(v.w - __bfloat162float(h3));
    __nv_bfloat162 ph0 = __nv_bfloat162(h0, h1), ph1 = __nv_bfloat162(h2, h3);
    __nv_bfloat162 pl0 = __nv_bfloat162(l0, l1), pl1 = __nv_bfloat162(l2, l3);
    uint2 uh = make_uint2(*(uint32_t*)&ph0, *(uint32_t*)&ph1);
    uint2 ul = make_uint2(*(uint32_t*)&pl0, *(uint32_t*)&pl1);
    ((uint2*)hi)[i] = uh;
    ((uint2*)lo)[i] = ul;
}

// ---------------------------------------------------------------------------
// Split-bf16 GEMM (NT) on mma.sync tensor cores.
// C[m,n] = sum_k A[m,k]*B[n,k] in fp32-equivalent precision
// (accumulates Ah*Bh + Ah*Bl + Al*Bh into fp32 register accumulators).
//
// CTA tile 128x128, 256 threads (8 warps, 4m x 2n), warp tile 32m x 64n.
// K staged in chunks of 64 bf16 (one 128B SW128 row), double-buffered smem.
// ldmatrix.x4 feeds m16n8k16 bf16 HMMAs.
// ---------------------------------------------------------------------------
#define BKC 64                       // bf16 K elements per stage
#define TILE_BYTES 16384             // 128 rows * 128 B
#define STAGE_BYTES (2 * TILE_BYTES) // A + B
#define GEMM_SMEM (2 * STAGE_BYTES)  // double buffered: 64 KB

// swizzled byte offset of 16B chunk c (0..7) in row r (0..127)
__device__ __forceinline__ uint32_t swz_off(uint32_t r, uint32_t c) {
    return r * 128 + ((c ^ (r & 7)) << 4);
}

__device__ __forceinline__ void gemm_mma_body(
    const __nv_bfloat16* __restrict__ Ah, const __nv_bfloat16* __restrict__ Al,
    const __nv_bfloat16* __restrict__ Bh, const __nv_bfloat16* __restrict__ Bl,
    float* __restrict__ C)
{
    extern __shared__ __align__(128) uint8_t dsm[];
    const uint32_t sb0 = smem_u32(dsm);

    const int tid = threadIdx.x;
    const int lane = tid & 31;
    const int wid = tid >> 5;
    const int wm = (wid >> 1) << 5;   // warp m offset: 0,32,64,96
    const int wn = (wid & 1) << 6;    // warp n offset: 0,64
    const int bm = blockIdx.y << 7;
    const int bn = blockIdx.x << 7;

    float acc[2][8][4];
#pragma unroll
    for (int mf = 0; mf < 2; ++mf)
#pragma unroll
        for (int nf = 0; nf < 8; ++nf)
#pragma unroll
            for (int e = 0; e < 4; ++e) acc[mf][nf][e] = 0.f;

    // loader geometry: 16B chunk id = tid + i*256; row = cid>>3, chunk = cid&7
    const int lrow = tid >> 3;        // base row for i=0 (rows advance by 32)
    const int lch  = tid & 7;

    // precomputed swizzled STS offsets (same for every stage)
    uint32_t sts_off[4];
#pragma unroll
    for (int i = 0; i < 4; ++i)
        sts_off[i] = swz_off(lrow + i * 32, lch);

    // precomputed ldmatrix base offsets (row-dependent part)
    // A frag mf: row = wm + mf*16 + (lane & 15), chunk = ks*2 + (lane>>4)
    // B frag pair p: row = wn + p*16 + ((lane>>4)<<3) + (lane&7),
    //                chunk = ks*2 + ((lane>>3)&1)
    const uint32_t a_row[2] = { (uint32_t)(wm + (lane & 15)),
                                (uint32_t)(wm + 16 + (lane & 15)) };
    const uint32_t a_chb = (uint32_t)(lane >> 4);
    uint32_t b_row[4];
#pragma unroll
    for (int p = 0; p < 4; ++p)
        b_row[p] = (uint32_t)(wn + p * 16 + ((lane >> 4) << 3) + (lane & 7));
    const uint32_t b_chb = (uint32_t)((lane >> 3) & 1);

    uint4 ra[4], rb[4];

#define LDG_STAGE(s_) { \
        const int t_ = (s_) >> 4; \
        const int kc_ = (s_) & 15; \
        const __nv_bfloat16* As_ = (t_ == 2) ? Al : Ah; \
        const __nv_bfloat16* Bs_ = (t_ == 1) ? Bl : Bh; \
        const __nv_bfloat16* ap_ = As_ + (size_t)(bm + lrow) * GD + kc_ * BKC + lch * 8; \
        const __nv_bfloat16* bp_ = Bs_ + (size_t)(bn + lrow) * GD + kc_ * BKC + lch * 8; \
        _Pragma("unroll") \
        for (int i_ = 0; i_ < 4; ++i_) { \
            ra[i_] = *(const uint4*)(ap_ + (size_t)i_ * 32 * GD); \
            rb[i_] = *(const uint4*)(bp_ + (size_t)i_ * 32 * GD); \
        } }

#define STS_STAGE(b_) { \
        const uint32_t ab_ = sb0 + (b_) * STAGE_BYTES; \
        const uint32_t bb_ = ab_ + TILE_BYTES; \
        _Pragma("unroll") \
        for (int i_ = 0; i_ < 4; ++i_) { \
            asm volatile("st.shared.v4.b32 [%0], {%1,%2,%3,%4};" \
                :: "r"(ab_ + sts_off[i_]), "r"(ra[i_].x), "r"(ra[i_].y), \
                   "r"(ra[i_].z), "r"(ra[i_].w) : "memory"); \
            asm volatile("st.shared.v4.b32 [%0], {%1,%2,%3,%4};" \
                :: "r"(bb_ + sts_off[i_]), "r"(rb[i_].x), "r"(rb[i_].y), \
                   "r"(rb[i_].z), "r"(rb[i_].w) : "memory"); \
        } }

    LDG_STAGE(0);
    STS_STAGE(0);
    __syncthreads();

#pragma unroll 1
    for (int s = 0; s < 48; ++s) {
        const uint32_t abase = sb0 + (s & 1) * STAGE_BYTES;
        const uint32_t bbase = abase + TILE_BYTES;

        if (s < 47) LDG_STAGE(s + 1);

#pragma unroll
        for (int ks = 0; ks < 4; ++ks) {
            uint32_t afr[2][4], bfr[4][4];
#pragma unroll
            for (int mf = 0; mf < 2; ++mf)
                ldsm_x4(abase + swz_off(a_row[mf], ks * 2 + a_chb), afr[mf]);
#pragma unroll
            for (int p = 0; p < 4; ++p)
                ldsm_x4(bbase + swz_off(b_row[p], ks * 2 + b_chb), bfr[p]);
#pragma unroll
            for (int mf = 0; mf < 2; ++mf)
#pragma unroll
                for (int nf = 0; nf < 8; ++nf)
                    mma_bf16(acc[mf][nf], afr[mf],
                             bfr[nf >> 1][(nf & 1) * 2],
                             bfr[nf >> 1][(nf & 1) * 2 + 1]);
        }

        if (s < 47) STS_STAGE((s + 1) & 1);
        __syncthreads();
    }
#undef LDG_STAGE
#undef STS_STAGE

    // epilogue: c-frag layout -> rows lane/4 (+8), cols 2*(lane&3) (+1)
    const int cr = lane >> 2;
    const int cc = (lane & 3) << 1;
#pragma unroll
    for (int mf = 0; mf < 2; ++mf) {
        float* r0 = C + (size_t)(bm + wm + mf * 16 + cr) * GD + bn + wn + cc;
        float* r1 = r0 + 8 * GD;
#pragma unroll
        for (int nf = 0; nf < 8; ++nf) {
            *(float2*)(r0 + nf * 8) = make_float2(acc[mf][nf][0], acc[mf][nf][1]);
            *(float2*)(r1 + nf * 8) = make_float2(acc[mf][nf][2], acc[mf][nf][3]);
        }
    }
}

// z = 0 -> K, 1 -> Q, 2 -> V
__global__ __launch_bounds__(256)
void qkv_mma_kernel()
{
    if (blockIdx.z == 0)      gemm_mma_body(g_xh, g_xl, g_Wkh, g_Wkl, g_K);
    else if (blockIdx.z == 1) gemm_mma_body(g_xh, g_xl, g_Wqh, g_Wql, g_Q);
    else                      gemm_mma_body(g_xh, g_xl, g_Wvh, g_Wvl, g_V);
}

__global__ __launch_bounds__(256)
void oproj_mma_kernel(float* __restrict__ out)
{
    gemm_mma_body(g_aoh, g_aol, g_Woh, g_Wol, out);
}

// ---------------------------------------------------------------------------
// Fast exp (FMA-only, for x <= 0; tolerant of -1e30 sentinels)
// ---------------------------------------------------------------------------
__device__ __forceinline__ float fexp(float x) {
    float y = fmaxf(x * 1.4426950408889634f, -126.0f);
    float r = y + 12582912.0f;
    int   n = __float_as_int(r) - 0x4B400000;
    float k = y - (r - 12582912.0f);
    float p = 1.3333558146428443e-3f;
    p = fmaf(p, k, 9.618129107628477e-3f);
    p = fmaf(p, k, 5.550410866482158e-2f);
    p = fmaf(p, k, 2.402265069591007e-1f);
    p = fmaf(p, k, 6.931471805599453e-1f);
    p = fmaf(p, k, 1.0f);
    return p * __int_as_float((n + 127) << 23);
}

// ---------------------------------------------------------------------------
// Flash-style causal attention, fp32 (unchanged, known-passing).
// ---------------------------------------------------------------------------
#define SWZ(rr, cc) (((cc) * 64) + ((((rr) >> 2) ^ ((cc) & 15)) << 2) + ((rr) & 3))

__global__ __launch_bounds__(256)
void flash_kernel()
{
    __shared__ float Qt[64 * 64];
    __shared__ float Kt[64 * 64];   // reused as Pt
    __shared__ float Vs[64 * 64];

    const int tid = threadIdx.x;
    const int tx = tid & 15;
    const int ty = tid >> 4;
    const int qt = blockIdx.x;
    const int bh = blockIdx.y;
    const int b = bh >> 4, h = bh & 15;

    const int base = b * GT * GD + h * HD;
    const float* qg = g_Q + base + qt * 64 * GD;

#pragma unroll
    for (int it = 0; it < 4; ++it) {
        int i = tid + it * 256;
        int r = i >> 4;
        int c4 = (i & 15) << 2;
        float4 v = *(const float4*)(qg + r * GD + c4);
        Qt[SWZ(r, c4 + 0)] = v.x;
        Qt[SWZ(r, c4 + 1)] = v.y;
        Qt[SWZ(r, c4 + 2)] = v.z;
        Qt[SWZ(r, c4 + 3)] = v.w;
    }

    float m[4], l[4], o[4][4];
#pragma unroll
    for (int i = 0; i < 4; ++i) {
        m[i] = -1e30f;
        l[i] = 0.f;
#pragma unroll
        for (int j = 0; j < 4; ++j) o[i][j] = 0.f;
    }

    const int r0 = ty << 2;
    const int c0 = tx << 2;

    for (int jt = 0; jt <= qt; ++jt) {
        const float* kg = g_K + base + jt * 64 * GD;
        const float* vg = g_V + base + jt * 64 * GD;

        __syncthreads();

#pragma unroll
        for (int it = 0; it < 4; ++it) {
            int i = tid + it * 256;
            int r = i >> 4;
            int c4 = (i & 15) << 2;
            float4 kv = *(const float4*)(kg + r * GD + c4);
            Kt[SWZ(r, c4 + 0)] = kv.x;
            Kt[SWZ(r, c4 + 1)] = kv.y;
            Kt[SWZ(r, c4 + 2)] = kv.z;
            Kt[SWZ(r, c4 + 3)] = kv.w;
            float4 vv = *(const float4*)(vg + r * GD + c4);
            *(float4*)&Vs[r * 64 + c4] = vv;
        }
        __syncthreads();

        float s[4][4];
#pragma unroll
        for (int i = 0; i < 4; ++i)
#pragma unroll
            for (int j = 0; j < 4; ++j) s[i][j] = 0.f;

#pragma unroll 16
        for (int hh = 0; hh < 64; ++hh) {
            const int sw = hh & 15;
            float4 qa = *(const float4*)&Qt[hh * 64 + ((ty ^ sw) << 2)];
            float4 kb = *(const float4*)&Kt[hh * 64 + ((tx ^ sw) << 2)];
            float ar[4] = {qa.x, qa.y, qa.z, qa.w};
            float br[4] = {kb.x, kb.y, kb.z, kb.w};
#pragma unroll
            for (int i = 0; i < 4; ++i)
#pragma unroll
                for (int j = 0; j < 4; ++j)
                    s[i][j] = fmaf(ar[i], br[j], s[i][j]);
        }

        const bool diag = (jt == qt);
#pragma unroll
        for (int i = 0; i < 4; ++i)
#pragma unroll
            for (int j = 0; j < 4; ++j) {
                float v = s[i][j] * 0.125f;
                if (diag && (c0 + j) > (r0 + i)) v = -1e30f;
                s[i][j] = v;
            }

#pragma unroll
        for (int i = 0; i < 4; ++i) {
            float rm = fmaxf(fmaxf(s[i][0], s[i][1]), fmaxf(s[i][2], s[i][3]));
            rm = fmaxf(rm, __shfl_xor_sync(0xffffffffu, rm, 1));
            rm = fmaxf(rm, __shfl_xor_sync(0xffffffffu, rm, 2));
            rm = fmaxf(rm, __shfl_xor_sync(0xffffffffu, rm, 4));
            rm = fmaxf(rm, __shfl_xor_sync(0xffffffffu, rm, 8));
            float mn = fmaxf(m[i], rm);
            float alpha = fexp(m[i] - mn);
            float rs = 0.f;
#pragma unroll
            for (int j = 0; j < 4; ++j) {
                float p = fexp(s[i][j] - mn);
                s[i][j] = p;
                rs += p;
            }
            rs += __shfl_xor_sync(0xffffffffu, rs, 1);
            rs += __shfl_xor_sync(0xffffffffu, rs, 2);
            rs += __shfl_xor_sync(0xffffffffu, rs, 4);
            rs += __shfl_xor_sync(0xffffffffu, rs, 8);
            l[i] = l[i] * alpha + rs;
            m[i] = mn;
#pragma unroll
            for (int j = 0; j < 4; ++j) o[i][j] *= alpha;
        }

        __syncthreads();

#pragma unroll
        for (int i = 0; i < 4; ++i)
#pragma unroll
            for (int j = 0; j < 4; ++j) {
                int c = c0 + j;
                Kt[c * 64 + ((ty ^ (c & 15)) << 2) + i] = s[i][j];
            }
        __syncthreads();

#pragma unroll 8
        for (int c = 0; c < 64; ++c) {
            float4 pa = *(const float4*)&Kt[c * 64 + ((ty ^ (c & 15)) << 2)];
            float4 vb = *(const float4*)&Vs[c * 64 + (tx << 2)];
            float ar[4] = {pa.x, pa.y, pa.z, pa.w};
            float br[4] = {vb.x, vb.y, vb.z, vb.w};
#pragma unroll
            for (int i = 0; i < 4; ++i)
#pragma unroll
                for (int j = 0; j < 4; ++j)
                    o[i][j] = fmaf(ar[i], br[j], o[i][j]);
        }
    }

    float* og = g_AO + base + qt * 64 * GD;
#pragma unroll
    for (int i = 0; i < 4; ++i) {
        float inv = 1.0f / l[i];
        float4 w = make_float4(o[i][0] * inv, o[i][1] * inv,
                               o[i][2] * inv, o[i][3] * inv);
        *(float4*)(og + (r0 + i) * GD + (tx << 2)) = w;
    }
}

// ---------------------------------------------------------------------------
// Launch sequence (graph-capturable, allocation-free).
// Inputs: x, Wk, Wq, Wv, Wo.
// ---------------------------------------------------------------------------
extern "C" void kernel_launch(void* const* d_in, const int* in_sizes, int n_in,
                              void* d_out, int out_size)
{
    const float* x  = (const float*)d_in[0];
    const float* Wk = (const float*)d_in[1];
    const float* Wq = (const float*)d_in[2];
    const float* Wv = (const float*)d_in[3];
    const float* Wo = (const float*)d_in[4];
    float* out = (float*)d_out;
    (void)in_sizes; (void)n_in; (void)out_size;

    static bool attr_done = false;
    if (!attr_done) {
        cudaFuncSetAttribute(qkv_mma_kernel,
                             cudaFuncAttributeMaxDynamicSharedMemorySize, GEMM_SMEM);
        cudaFuncSetAttribute(oproj_mma_kernel,
                             cudaFuncAttributeMaxDynamicSharedMemorySize, GEMM_SMEM);
        attr_done = true;
    }

    // resolve device-symbol addresses for conversion targets (host API, no alloc)
    __nv_bfloat16 *xh, *xl, *aoh, *aol;
    __nv_bfloat16 *wkh, *wkl, *wqh, *wql, *wvh, *wvl, *woh, *wol;
    float *ao;
    cudaGetSymbolAddress((void**)&xh,  g_xh);
    cudaGetSymbolAddress((void**)&xl,  g_xl);
    cudaGetSymbolAddress((void**)&aoh, g_aoh);
    cudaGetSymbolAddress((void**)&aol, g_aol);
    cudaGetSymbolAddress((void**)&wkh, g_Wkh);
    cudaGetSymbolAddress((void**)&wkl, g_Wkl);
    cudaGetSymbolAddress((void**)&wqh, g_Wqh);
    cudaGetSymbolAddress((void**)&wql, g_Wql);
    cudaGetSymbolAddress((void**)&wvh, g_Wvh);
    cudaGetSymbolAddress((void**)&wvl, g_Wvl);
    cudaGetSymbolAddress((void**)&woh, g_Woh);
    cudaGetSymbolAddress((void**)&wol, g_Wol);
    cudaGetSymbolAddress((void**)&ao,  g_AO);

    const int n4x = GM * GD / 4;   // 2,097,152
    const int n4w = GD * GD / 4;   // 262,144

    conv_split_kernel<<<n4x / 256, 256>>>(x, xh, xl, n4x);
    conv_split_kernel<<<n4w / 256, 256>>>(Wk, wkh, wkl, n4w);
    conv_split_kernel<<<n4w / 256, 256>>>(Wq, wqh, wql, n4w);
    conv_split_kernel<<<n4w / 256, 256>>>(Wv, wvh, wvl, n4w);
    conv_split_kernel<<<n4w / 256, 256>>>(Wo, woh, wol, n4w);

    qkv_mma_kernel<<<dim3(GD / 128, GM / 128, 3), 256, GEMM_SMEM>>>();

    flash_kernel<<<dim3(GT / 64, GB * NHEAD), 256>>>();

    conv_split_kernel<<<n4x / 256, 256>>>(ao, aoh, aol, n4x);
    oproj_mma_kernel<<<dim3(GD / 128, GM / 128), 256, GEMM_SMEM>>>(out);
}